// round 13
// baseline (speedup 1.0000x reference)
#include <cuda_runtime.h>
#include <cuda_bf16.h>
#include <math.h>
#include <stdint.h>

#define BB 8
#define CC 64
#define OO 64
#define HH 128
#define WW 128
#define HWSZ (HH*WW)            // 16384
#define NPIX (BB*HWSZ)          // 131072
#define TPB 256

typedef unsigned long long ull;

// ---------------- scratch (allocation-free: __device__ globals) --------------
__device__ float          g_wom_t[CC*9*28];         // [c][t][j]
__device__ float4         g_cw4[(size_t)NPIX*9];    // per (p,k): 4 corner weights
__device__ int4           g_ci4[(size_t)NPIX*9];    // per (p,k): 4 clamped hw indices
__device__ float          g_xt[(size_t)NPIX*CC];    // [b][hw][c] (33.5 MB, L2-resident)
__device__ __nv_bfloat16  g_Wbh[9*64*64];           // W hi: [k][o][c] 128B rows
__device__ __nv_bfloat16  g_Wbl[9*64*64];           // W lo

// ---------------- packed f32x2 helpers ---------------------------------------
__device__ __forceinline__ ull pk2(float lo, float hi){
    ull r; asm("mov.b64 %0, {%1,%2};" : "=l"(r) : "f"(lo), "f"(hi)); return r;
}
__device__ __forceinline__ void upk2(ull v, float& lo, float& hi){
    asm("mov.b64 {%0,%1}, %2;" : "=f"(lo), "=f"(hi) : "l"(v));
}
__device__ __forceinline__ ull f2fma(ull a, ull b, ull c){
    ull d; asm("fma.rn.f32x2 %0, %1, %2, %3;" : "=l"(d) : "l"(a), "l"(b), "l"(c)); return d;
}
__device__ __forceinline__ ull ldg2(const float* p){
    ull v; asm("ld.global.nc.b64 %0, [%1];" : "=l"(v) : "l"(p)); return v;
}
__device__ __forceinline__ uint32_t smem_u32(const void* p){
    uint32_t a;
    asm("{ .reg .u64 t; cvta.to.shared.u64 t, %1; cvt.u32.u64 %0, t; }" : "=r"(a) : "l"(p));
    return a;
}
__device__ __forceinline__ void ldsm4(uint32_t* r, uint32_t addr){
    asm volatile("ldmatrix.sync.aligned.m8n8.x4.shared.b16 {%0,%1,%2,%3}, [%4];"
        : "=r"(r[0]), "=r"(r[1]), "=r"(r[2]), "=r"(r[3]) : "r"(addr));
}
__device__ __forceinline__ void hmma(float* d, const uint32_t* a, uint32_t b0, uint32_t b1){
    asm volatile("mma.sync.aligned.m16n8k16.row.col.f32.bf16.bf16.f32 "
        "{%0,%1,%2,%3}, {%4,%5,%6,%7}, {%8,%9}, {%0,%1,%2,%3};"
        : "+f"(d[0]), "+f"(d[1]), "+f"(d[2]), "+f"(d[3])
        : "r"(a[0]), "r"(a[1]), "r"(a[2]), "r"(a[3]), "r"(b0), "r"(b1));
}
#define BAR_SYNC(id,count)   asm volatile("bar.sync %0, %1;"   :: "r"(id), "r"(count) : "memory")
#define BAR_ARRIVE(id,count) asm volatile("bar.arrive %0, %1;" :: "r"(id), "r"(count) : "memory")

// ---------------- prep: W -> bf16 hi/lo [k][o][c]; offmask weights -----------
__global__ void k_prep(const float* __restrict__ wm,
                       const float* __restrict__ wo,
                       const float* __restrict__ wk){
    int i = blockIdx.x*TPB + threadIdx.x;
    if (i < 9*64*64){
        int k = i >> 12; int o = (i >> 6) & 63; int c = i & 63;
        float w = wm[(o*CC + c)*9 + k];
        __nv_bfloat16 h = __float2bfloat16(w);
        float r = w - __bfloat162float(h);
        g_Wbh[i] = h;
        g_Wbl[i] = __float2bfloat16(r);
    }
    int j2 = i - 9*64*64;
    if (j2 >= 0 && j2 < CC*9*28){
        int ct = j2/28; int j = j2 - ct*28; int c = ct/9; int t = ct - c*9;
        float v = 0.f;
        if (j < 18)      v = wo[(j*CC + c)*9 + t];
        else if (j < 27) v = wk[((j-18)*CC + c)*9 + t];
        g_wom_t[j2] = v;
    }
}

// ---------------- P0: x [b][c][hw] -> g_xt [b][hw][c] -------------------------
__global__ void k_xt(const float* __restrict__ x){
    __shared__ float t[32][33];
    int b  = blockIdx.z;
    int c0 = blockIdx.y*32;
    int hw0= blockIdx.x*32;
    const float* xb = x + ((size_t)b*CC + c0)*HWSZ + hw0;
    for (int i = threadIdx.y; i < 32; i += 8)
        t[i][threadIdx.x] = xb[(size_t)i*HWSZ + threadIdx.x];
    __syncthreads();
    float* xtb = g_xt + ((size_t)b*HWSZ + hw0)*CC + c0;
    for (int i = threadIdx.y; i < 32; i += 8)
        xtb[(size_t)i*CC + threadIdx.x] = t[threadIdx.x][i];
}

// ---- P1: offset(18)+mask(9) 3x3 conv; emit folded corner wgts/idx -----------
__global__ void __launch_bounds__(TPB)
k_offmask(const float* __restrict__ x,
          const float* __restrict__ boff,
          const float* __restrict__ bmsk){
    __shared__ __align__(16) float s_wom[32*9*28];

    int p   = blockIdx.x*TPB + threadIdx.x;
    int b   = p >> 14;
    int hw  = p & (HWSZ-1);
    int h   = hw >> 7;
    int wp  = hw & (WW-1);
    const float* xb = x + (size_t)b*CC*HWSZ;

    ull acc[14];
    #pragma unroll
    for (int q=0;q<14;q++){
        int j0=2*q, j1=2*q+1;
        float lo = (j0<18)? boff[j0] : (j0<27 ? bmsk[j0-18] : 0.f);
        float hi = (j1<18)? boff[j1] : (j1<27 ? bmsk[j1-18] : 0.f);
        acc[q] = pk2(lo,hi);
    }

    for (int cc=0; cc<CC; cc+=32){
        __syncthreads();
        for (int i=threadIdx.x; i<32*9*28; i+=TPB)
            s_wom[i] = g_wom_t[cc*9*28 + i];
        __syncthreads();

        for (int c=0;c<32;c++){
            const float* xc = xb + (cc+c)*HWSZ;
            float v[9];
            #pragma unroll
            for (int t=0;t<9;t++){
                int yy = h + t/3 - 1, xx = wp + t%3 - 1;
                v[t] = (yy>=0 && yy<HH && xx>=0 && xx<WW) ? __ldg(xc + yy*WW + xx) : 0.f;
            }
            #pragma unroll
            for (int t=0;t<9;t++){
                ull vv = pk2(v[t], v[t]);
                const ulonglong2* wq = (const ulonglong2*)&s_wom[(c*9+t)*28];
                #pragma unroll
                for (int q=0;q<7;q++){
                    ulonglong2 ww = wq[q];
                    acc[2*q]   = f2fma(vv, ww.x, acc[2*q]);
                    acc[2*q+1] = f2fma(vv, ww.y, acc[2*q+1]);
                }
            }
        }
    }

    #pragma unroll
    for (int k=0;k<9;k++){
        float dy, dx; upk2(acc[k], dy, dx);
        float mlo, mhi; upk2(acc[9 + k/2], mlo, mhi);
        float mraw = (k & 1) ? mhi : mlo;
        float mk = 1.f/(1.f + expf(-mraw));

        float py = dy + (float)(h + k/3 - 1);
        float px = dx + (float)(wp + k%3 - 1);
        float y0f = floorf(py), x0f = floorf(px);
        float ly = py - y0f, lx = px - x0f;
        int y0 = (int)y0f, x0 = (int)x0f;
        int y1 = y0 + 1,   x1 = x0 + 1;

        float vy0 = (y0>=0 && y0<HH) ? 1.f : 0.f;
        float vy1 = (y1>=0 && y1<HH) ? 1.f : 0.f;
        float vx0 = (x0>=0 && x0<WW) ? 1.f : 0.f;
        float vx1 = (x1>=0 && x1<WW) ? 1.f : 0.f;

        float w00 = (1.f-ly)*(1.f-lx)*vy0*vx0*mk;
        float w01 = (1.f-ly)*lx      *vy0*vx1*mk;
        float w10 = ly      *(1.f-lx)*vy1*vx0*mk;
        float w11 = ly      *lx      *vy1*vx1*mk;

        int y0c = min(max(y0,0),HH-1), y1c = min(max(y1,0),HH-1);
        int x0c = min(max(x0,0),WW-1), x1c = min(max(x1,0),WW-1);

        g_cw4[(size_t)p*9 + k] = make_float4(w00,w01,w10,w11);
        g_ci4[(size_t)p*9 + k] = make_int4(y0c*WW+x0c, y0c*WW+x1c,
                                           y1c*WW+x0c, y1c*WW+x1c);
    }
}

// ---- P2: warp-specialized fused gather + HMMA --------------------------------
// CTA = 32 px x 64 o. Warps 0-3 produce (gather+convert, double-buffered A);
// warps 4-7 consume (B load + ldsm + 3-pass HMMA). Named barriers:
//   full0=1, full1=2 (producers arrive, consumers sync, 256)
//   empty0=3, empty1=4 (consumers arrive, producers sync, 256)
//   id 5: consumer-only B-buffer guard (128)
__global__ void __launch_bounds__(TPB)
k_fuse(float* __restrict__ out){
    __shared__ __align__(16) uint4 smem[2304];   // 36864 B
    // [0,576)    A buf0: hi 288 | lo 288   (32 rows x 9 uint4 each)
    // [576,1152) A buf1
    // [1152,1728) B hi (64 rows x 9)
    // [1728,2304) B lo
    uint32_t* wA = (uint32_t*)smem;

    int t = threadIdx.x, l = t & 31, w = t >> 5;
    int p0 = blockIdx.x*32;
    int b  = p0 >> 14;
    int hw0= p0 & (HWSZ-1);
    uint32_t smemB = smem_u32(smem);

    float acc[4][4];
    #pragma unroll
    for (int i=0;i<4;i++){ acc[i][0]=0.f; acc[i][1]=0.f; acc[i][2]=0.f; acc[i][3]=0.f; }

    if (w < 4){
        // ---------------- producers ----------------
        const float* xtb = g_xt + (size_t)b*HWSZ*CC;
        for (int kc=0; kc<9; kc++){
            int buf = kc & 1;
            if (kc >= 2) BAR_SYNC(3+buf, 256);
            #pragma unroll
            for (int j=0;j<8;j++){
                int px = w*8 + j;
                size_t pk = (size_t)(p0+px)*9 + kc;
                float4 wq = __ldg(&g_cw4[pk]);
                int4   iq = __ldg(&g_ci4[pk]);
                ull v;
                v = f2fma(pk2(wq.x,wq.x), ldg2(xtb + (size_t)iq.x*CC + 2*l), 0ull);
                v = f2fma(pk2(wq.y,wq.y), ldg2(xtb + (size_t)iq.y*CC + 2*l), v);
                v = f2fma(pk2(wq.z,wq.z), ldg2(xtb + (size_t)iq.z*CC + 2*l), v);
                v = f2fma(pk2(wq.w,wq.w), ldg2(xtb + (size_t)iq.w*CC + 2*l), v);
                float f0,f1; upk2(v,f0,f1);
                uint32_t ph;
                asm("cvt.rn.bf16x2.f32 %0, %1, %2;" : "=r"(ph) : "f"(f1), "f"(f0));
                uint32_t h0b = ph<<16, h1b = ph & 0xffff0000u;
                ull hp;  asm("mov.b64 %0, {%1,%2};" : "=l"(hp) : "r"(h0b), "r"(h1b));
                ull lo2; asm("sub.rn.f32x2 %0, %1, %2;" : "=l"(lo2) : "l"(v), "l"(hp));
                float g0,g1; upk2(lo2,g0,g1);
                uint32_t pl;
                asm("cvt.rn.bf16x2.f32 %0, %1, %2;" : "=r"(pl) : "f"(g1), "f"(g0));
                wA[buf*2304 + px*36 + l]        = ph;   // 144B rows, conflict-free
                wA[buf*2304 + 1152 + px*36 + l] = pl;
            }
            __threadfence_block();
            BAR_ARRIVE(1+buf, 256);
        }
    } else {
        // ---------------- consumers ----------------
        int ct = t - 128;
        int cw = ct >> 5;
        int m0 = (cw & 1)*16;        // 16-px slice
        int n0 = (cw >> 1)*32;       // 32-o slice
        int brow = ct >> 1, q4 = (ct & 1)*4;

        int a_row = (l & 7) + ((l >> 3) & 1)*8;
        int a_kb  = l >> 4;
        int b_row = (l & 7) + (l >> 4)*8;
        int b_kb  = (l >> 3) & 1;

        for (int kc=0; kc<9; kc++){
            int buf = kc & 1;
            // B hi prefetch to regs, then staged STS around the guard barrier
            const uint4* gBh = (const uint4*)(g_Wbh + (size_t)kc*4096 + brow*64);
            const uint4* gBl = (const uint4*)(g_Wbl + (size_t)kc*4096 + brow*64);
            uint4 rh[4];
            #pragma unroll
            for (int u=0;u<4;u++) rh[u] = __ldg(gBh + q4 + u);
            BAR_SYNC(5, 128);                      // prior stage's B ldsm complete
            #pragma unroll
            for (int u=0;u<4;u++) smem[1152 + brow*9 + q4 + u] = rh[u];
            #pragma unroll
            for (int u=0;u<4;u++) rh[u] = __ldg(gBl + q4 + u);
            #pragma unroll
            for (int u=0;u<4;u++) smem[1728 + brow*9 + q4 + u] = rh[u];

            BAR_SYNC(1+buf, 256);                  // A[buf] full (also drains B STS)

            uint32_t aB = smemB + (uint32_t)buf*9216u;
            #pragma unroll
            for (int ks=0; ks<4; ks++){
                uint32_t ah[4], al[4], bh[2][4], bl[2][4];
                uint32_t offA = (uint32_t)((m0 + a_row)*9 + ks*2 + a_kb)*16u;
                ldsm4(ah, aB + offA);
                ldsm4(al, aB + 4608u + offA);
                #pragma unroll
                for (int nf2=0; nf2<2; nf2++){
                    uint32_t offB = (uint32_t)((n0 + nf2*16 + b_row)*9 + ks*2 + b_kb)*16u;
                    ldsm4(bh[nf2], smemB + 18432u + offB);
                    ldsm4(bl[nf2], smemB + 27648u + offB);
                }
                #pragma unroll
                for (int nf=0; nf<4; nf++){
                    uint32_t h0 = bh[nf>>1][(nf&1)*2], h1 = bh[nf>>1][(nf&1)*2+1];
                    uint32_t l0 = bl[nf>>1][(nf&1)*2], l1 = bl[nf>>1][(nf&1)*2+1];
                    hmma(acc[nf], ah, h0, h1);     // hi*hi
                    hmma(acc[nf], ah, l0, l1);     // hi*lo
                    hmma(acc[nf], al, h0, h1);     // lo*hi
                }
            }
            if (kc <= 6) BAR_ARRIVE(3+buf, 256);   // A[buf] empty
        }
    }

    // ---- epilogue: consumers stage [o][px pad36], everyone stores ------------
    __syncthreads();
    float* st = (float*)smem;   // 64*36*4 = 9216 B
    if (w >= 4){
        int ct = t - 128;
        int cw = ct >> 5;
        int m0 = (cw & 1)*16;
        int n0 = (cw >> 1)*32;
        int group = l >> 2, tid4 = l & 3;
        int r0 = m0 + group;
        #pragma unroll
        for (int nf=0; nf<4; nf++){
            int o = n0 + nf*8 + 2*tid4;
            st[(size_t)o    *36 + r0    ] = acc[nf][0];
            st[(size_t)(o+1)*36 + r0    ] = acc[nf][1];
            st[(size_t)o    *36 + r0 + 8] = acc[nf][2];
            st[(size_t)(o+1)*36 + r0 + 8] = acc[nf][3];
        }
    }
    __syncthreads();
    {
        int o = t >> 2, seg = (t & 3)*8;
        float* op = out + ((size_t)(b*OO + o))*HWSZ + hw0 + seg;
        *(float4*)(op)     = *(float4*)&st[(size_t)o*36 + seg];
        *(float4*)(op + 4) = *(float4*)&st[(size_t)o*36 + seg + 4];
    }
}

// ---------------- launch ------------------------------------------------------
extern "C" void kernel_launch(void* const* d_in, const int* in_sizes, int n_in,
                              void* d_out, int out_size){
    const float* x        = (const float*)d_in[0];
    const float* w_main   = (const float*)d_in[1];
    const float* w_offset = (const float*)d_in[2];
    const float* b_offset = (const float*)d_in[3];
    const float* w_mask   = (const float*)d_in[4];
    const float* b_mask   = (const float*)d_in[5];
    float* out = (float*)d_out;

    int prep_n = 9*64*64 + CC*9*28;
    k_prep<<<(prep_n + TPB-1)/TPB, TPB>>>(w_main, w_offset, w_mask);
    dim3 gx(HWSZ/32, CC/32, BB);
    k_xt<<<gx, dim3(32,8)>>>(x);
    k_offmask<<<NPIX/TPB, TPB>>>(x, b_offset, b_mask);
    k_fuse<<<NPIX/32, TPB>>>(out);
}

// round 14
// speedup vs baseline: 1.2841x; 1.2841x over previous
#include <cuda_runtime.h>
#include <cuda_bf16.h>
#include <math.h>
#include <stdint.h>

#define BB 8
#define CC 64
#define OO 64
#define HH 128
#define WW 128
#define HWSZ (HH*WW)            // 16384
#define NPIX (BB*HWSZ)          // 131072
#define TPB 256

typedef unsigned long long ull;

// ---------------- scratch (allocation-free: __device__ globals) --------------
__device__ float4         g_cw4[(size_t)NPIX*9];    // per (p,k): 4 corner weights
__device__ int4           g_ci4[(size_t)NPIX*9];    // per (p,k): 4 clamped hw indices
__device__ float          g_xt[(size_t)NPIX*CC];    // [b][hw][c] (33.5 MB, L2-resident)
__device__ __nv_bfloat16  g_Wbh[9*64*64];           // main W hi: [k][o][c] 128B rows
__device__ __nv_bfloat16  g_Wbl[9*64*64];           // main W lo
__device__ __nv_bfloat16  g_OMbh[9*32*64];          // off/mask W hi: [t][j(32)][c]
__device__ __nv_bfloat16  g_OMbl[9*32*64];          // off/mask W lo

// ---------------- packed f32x2 helpers ---------------------------------------
__device__ __forceinline__ ull pk2(float lo, float hi){
    ull r; asm("mov.b64 %0, {%1,%2};" : "=l"(r) : "f"(lo), "f"(hi)); return r;
}
__device__ __forceinline__ void upk2(ull v, float& lo, float& hi){
    asm("mov.b64 {%0,%1}, %2;" : "=f"(lo), "=f"(hi) : "l"(v));
}
__device__ __forceinline__ ull f2fma(ull a, ull b, ull c){
    ull d; asm("fma.rn.f32x2 %0, %1, %2, %3;" : "=l"(d) : "l"(a), "l"(b), "l"(c)); return d;
}
__device__ __forceinline__ ull ldg2(const float* p){
    ull v; asm("ld.global.nc.b64 %0, [%1];" : "=l"(v) : "l"(p)); return v;
}
__device__ __forceinline__ uint32_t smem_u32(const void* p){
    uint32_t a;
    asm("{ .reg .u64 t; cvta.to.shared.u64 t, %1; cvt.u32.u64 %0, t; }" : "=r"(a) : "l"(p));
    return a;
}
__device__ __forceinline__ void ldsm4(uint32_t* r, uint32_t addr){
    asm volatile("ldmatrix.sync.aligned.m8n8.x4.shared.b16 {%0,%1,%2,%3}, [%4];"
        : "=r"(r[0]), "=r"(r[1]), "=r"(r[2]), "=r"(r[3]) : "r"(addr));
}
__device__ __forceinline__ void hmma(float* d, const uint32_t* a, uint32_t b0, uint32_t b1){
    asm volatile("mma.sync.aligned.m16n8k16.row.col.f32.bf16.bf16.f32 "
        "{%0,%1,%2,%3}, {%4,%5,%6,%7}, {%8,%9}, {%0,%1,%2,%3};"
        : "+f"(d[0]), "+f"(d[1]), "+f"(d[2]), "+f"(d[3])
        : "r"(a[0]), "r"(a[1]), "r"(a[2]), "r"(a[3]), "r"(b0), "r"(b1));
}
// packed fp32x2 -> bf16x2 hi + bf16x2 lo (residual), 6 instrs
__device__ __forceinline__ void cvt_hilo(ull v, uint32_t& ph, uint32_t& pl){
    float f0,f1; upk2(v,f0,f1);
    asm("cvt.rn.bf16x2.f32 %0, %1, %2;" : "=r"(ph) : "f"(f1), "f"(f0));
    uint32_t h0b = ph<<16, h1b = ph & 0xffff0000u;
    ull hp;  asm("mov.b64 %0, {%1,%2};" : "=l"(hp) : "r"(h0b), "r"(h1b));
    ull lo2; asm("sub.rn.f32x2 %0, %1, %2;" : "=l"(lo2) : "l"(v), "l"(hp));
    float g0,g1; upk2(lo2,g0,g1);
    asm("cvt.rn.bf16x2.f32 %0, %1, %2;" : "=r"(pl) : "f"(g1), "f"(g0));
}

// ---------------- prep: main W + off/mask W -> bf16 hi/lo ---------------------
__global__ void k_prep(const float* __restrict__ wm,
                       const float* __restrict__ wo,
                       const float* __restrict__ wk){
    int i = blockIdx.x*TPB + threadIdx.x;
    if (i < 9*64*64){
        int k = i >> 12; int o = (i >> 6) & 63; int c = i & 63;
        float w = wm[(o*CC + c)*9 + k];
        __nv_bfloat16 h = __float2bfloat16(w);
        float r = w - __bfloat162float(h);
        g_Wbh[i] = h;
        g_Wbl[i] = __float2bfloat16(r);
    }
    int j2 = i - 9*64*64;
    if (j2 >= 0 && j2 < 9*32*64){
        int tp = j2 >> 11; int j = (j2 >> 6) & 31; int c = j2 & 63;
        float v = 0.f;
        if (j < 18)      v = wo[(j*CC + c)*9 + tp];
        else if (j < 27) v = wk[((j-18)*CC + c)*9 + tp];
        __nv_bfloat16 h = __float2bfloat16(v);
        float r = v - __bfloat162float(h);
        g_OMbh[j2] = h;
        g_OMbl[j2] = __float2bfloat16(r);
    }
}

// ---------------- P0: x [b][c][hw] -> g_xt [b][hw][c] -------------------------
__global__ void k_xt(const float* __restrict__ x){
    __shared__ float t[32][33];
    int b  = blockIdx.z;
    int c0 = blockIdx.y*32;
    int hw0= blockIdx.x*32;
    const float* xb = x + ((size_t)b*CC + c0)*HWSZ + hw0;
    for (int i = threadIdx.y; i < 32; i += 8)
        t[i][threadIdx.x] = xb[(size_t)i*HWSZ + threadIdx.x];
    __syncthreads();
    float* xtb = g_xt + ((size_t)b*HWSZ + hw0)*CC + c0;
    for (int i = threadIdx.y; i < 32; i += 8)
        xtb[(size_t)i*CC + threadIdx.x] = t[threadIdx.x][i];
}

// ---- P1: offset+mask conv as HMMA GEMM (M=128px/CTA, N=32(27), K=576) -------
// Per tap: gather 128 neighbor rows of x_t (sequential 256B reads, zero-pad
// at borders), convert bf16 hi/lo into 144B-row smem, 3-pass HMMA accumulate.
// Epilogue: stage D[128][28], one thread/pixel folds sigmoid+bilinear weights.
__global__ void __launch_bounds__(TPB)
k_om(const float* __restrict__ boff, const float* __restrict__ bmsk){
    __shared__ __align__(16) uint4 smem[2880];   // 46080 B
    // [0,1152)    A hi: 128 rows x 9 uint4 (144B rows)
    // [1152,2304) A lo
    // [2304,2592) B hi: 32 rows x 9
    // [2592,2880) B lo
    uint32_t* wA = (uint32_t*)smem;

    int t = threadIdx.x, l = t & 31, w = t >> 5;
    int p0 = blockIdx.x*128;
    int b  = p0 >> 14;
    const float* xtb = g_xt + (size_t)b*HWSZ*CC;

    int m0 = (w >> 1)*32;     // 4 m-tiles of 32 px
    int n0 = (w & 1)*16;      // 2 n-tiles of 16

    uint32_t aBase = smem_u32(smem);

    float acc[2][2][4];
    #pragma unroll
    for (int i=0;i<2;i++)
        #pragma unroll
        for (int j=0;j<2;j++)
            #pragma unroll
            for (int q=0;q<4;q++) acc[i][j][q] = 0.f;

    int a_row = (l & 7) + ((l >> 3) & 1)*8;
    int a_kb  = l >> 4;
    int b_row = (l & 7) + (l >> 4)*8;
    int b_kb  = (l >> 3) & 1;
    int brow = t >> 3, bu = t & 7;   // B: 8 thr/row, 1 uint4 each

    for (int tap=0; tap<9; tap++){
        __syncthreads();
        // ---- B load (32x64 bf16 hi/lo)
        smem[2304 + brow*9 + bu] = __ldg((const uint4*)(g_OMbh + (size_t)tap*2048 + brow*64) + bu);
        smem[2592 + brow*9 + bu] = __ldg((const uint4*)(g_OMbl + (size_t)tap*2048 + brow*64) + bu);
        // ---- A gather: warp handles 16 px; lane covers channels 2l,2l+1
        int dh = tap/3 - 1, dw = tap%3 - 1;
        #pragma unroll
        for (int j=0;j<16;j++){
            int px = w*16 + j;
            int hw = (p0 + px) & (HWSZ-1);
            int h = hw >> 7, wc = hw & (WW-1);
            ull v = 0ull;
            if ((unsigned)(h+dh) < HH && (unsigned)(wc+dw) < WW)
                v = ldg2(xtb + (size_t)(hw + dh*WW + dw)*CC + 2*l);
            uint32_t ph, pl; cvt_hilo(v, ph, pl);
            wA[px*36 + l]        = ph;
            wA[4608 + px*36 + l] = pl;
        }
        __syncthreads();

        // ---- HMMA 3-pass
        #pragma unroll
        for (int ks=0; ks<4; ks++){
            uint32_t ah[2][4], al[2][4], bh[4], bl[4];
            #pragma unroll
            for (int mf=0; mf<2; mf++){
                uint32_t offA = (uint32_t)((m0 + mf*16 + a_row)*9 + ks*2 + a_kb)*16u;
                ldsm4(ah[mf], aBase + offA);
                ldsm4(al[mf], aBase + 18432u + offA);
            }
            {
                uint32_t offB = (uint32_t)((n0 + b_row)*9 + ks*2 + b_kb)*16u;
                ldsm4(bh, aBase + 36864u + offB);
                ldsm4(bl, aBase + 41472u + offB);
            }
            #pragma unroll
            for (int mf=0; mf<2; mf++){
                #pragma unroll
                for (int nf=0; nf<2; nf++){
                    hmma(acc[mf][nf], ah[mf], bh[nf*2], bh[nf*2+1]);
                    hmma(acc[mf][nf], ah[mf], bl[nf*2], bl[nf*2+1]);
                    hmma(acc[mf][nf], al[mf], bh[nf*2], bh[nf*2+1]);
                }
            }
        }
    }

    // ---- stage D[px][28] then per-pixel epilogue -----------------------------
    __syncthreads();
    float* st = (float*)smem;   // 128*28*4 = 14336 B
    {
        int group = l >> 2, tid4 = l & 3;
        #pragma unroll
        for (int mf=0; mf<2; mf++){
            int r0 = m0 + mf*16 + group;
            #pragma unroll
            for (int nf=0; nf<2; nf++){
                int o = n0 + nf*8 + 2*tid4;
                if (o < 28){
                    st[r0*28 + o]       = acc[mf][nf][0];
                    st[r0*28 + o+1]     = acc[mf][nf][1];
                    st[(r0+8)*28 + o]   = acc[mf][nf][2];
                    st[(r0+8)*28 + o+1] = acc[mf][nf][3];
                }
            }
        }
    }
    __syncthreads();
    if (t < 128){
        int p  = p0 + t;
        int hw = p & (HWSZ-1);
        int h  = hw >> 7;
        int wp = hw & (WW-1);
        const float* row = st + t*28;
        #pragma unroll
        for (int k=0;k<9;k++){
            float dy   = row[2*k]   + boff[2*k];
            float dx   = row[2*k+1] + boff[2*k+1];
            float mraw = row[18+k]  + bmsk[k];
            float mk = 1.f/(1.f + expf(-mraw));

            float py = dy + (float)(h + k/3 - 1);
            float px = dx + (float)(wp + k%3 - 1);
            float y0f = floorf(py), x0f = floorf(px);
            float ly = py - y0f, lx = px - x0f;
            int y0 = (int)y0f, x0 = (int)x0f;
            int y1 = y0 + 1,   x1 = x0 + 1;

            float vy0 = (y0>=0 && y0<HH) ? 1.f : 0.f;
            float vy1 = (y1>=0 && y1<HH) ? 1.f : 0.f;
            float vx0 = (x0>=0 && x0<WW) ? 1.f : 0.f;
            float vx1 = (x1>=0 && x1<WW) ? 1.f : 0.f;

            float w00 = (1.f-ly)*(1.f-lx)*vy0*vx0*mk;
            float w01 = (1.f-ly)*lx      *vy0*vx1*mk;
            float w10 = ly      *(1.f-lx)*vy1*vx0*mk;
            float w11 = ly      *lx      *vy1*vx1*mk;

            int y0c = min(max(y0,0),HH-1), y1c = min(max(y1,0),HH-1);
            int x0c = min(max(x0,0),WW-1), x1c = min(max(x1,0),WW-1);

            g_cw4[(size_t)p*9 + k] = make_float4(w00,w01,w10,w11);
            g_ci4[(size_t)p*9 + k] = make_int4(y0c*WW+x0c, y0c*WW+x1c,
                                               y1c*WW+x0c, y1c*WW+x1c);
        }
    }
}

// ---- P2: fused gather + HMMA GEMM (R12 structure, cheaper convert) ----------
__global__ void __launch_bounds__(TPB)
k_fuse(float* __restrict__ out){
    __shared__ __align__(16) uint4 smem[4*576];   // Ahi|Alo|Bh|Bl, 36864 B
    uint4* sBh = smem + 2*576;
    uint4* sBl = smem + 3*576;
    uint32_t* wAhi = (uint32_t*)smem;
    uint32_t* wAlo = (uint32_t*)(smem + 576);

    int t = threadIdx.x, l = t & 31, w = t >> 5;
    int p0 = blockIdx.x*64;
    int b  = p0 >> 14;
    int hw0= p0 & (HWSZ-1);
    const float* xtb = g_xt + (size_t)b*HWSZ*CC;

    int m0 = (w & 1)*32;
    int n0 = (w >> 1)*16;

    uint32_t aBase  = smem_u32(smem);
    uint32_t alBase = aBase + 576*16;
    uint32_t bhBase = aBase + 2*576*16;
    uint32_t blBase = aBase + 3*576*16;

    float acc[2][2][4];
    #pragma unroll
    for (int i=0;i<2;i++)
        #pragma unroll
        for (int j=0;j<2;j++)
            #pragma unroll
            for (int q=0;q<4;q++) acc[i][j][q] = 0.f;

    int a_row = (l & 7) + ((l >> 3) & 1)*8;
    int a_kb  = l >> 4;
    int b_row = (l & 7) + (l >> 4)*8;
    int b_kb  = (l >> 3) & 1;
    int brow = t >> 2, bq2 = (t & 3)*2;

    for (int kc=0; kc<9; kc++){
        __syncthreads();
        #pragma unroll
        for (int j=0;j<8;j++){
            int px = w*8 + j;
            size_t pk = (size_t)(p0+px)*9 + kc;
            float4 wq = __ldg(&g_cw4[pk]);
            int4   iq = __ldg(&g_ci4[pk]);
            ull v;
            v = f2fma(pk2(wq.x,wq.x), ldg2(xtb + (size_t)iq.x*CC + 2*l), 0ull);
            v = f2fma(pk2(wq.y,wq.y), ldg2(xtb + (size_t)iq.y*CC + 2*l), v);
            v = f2fma(pk2(wq.z,wq.z), ldg2(xtb + (size_t)iq.z*CC + 2*l), v);
            v = f2fma(pk2(wq.w,wq.w), ldg2(xtb + (size_t)iq.w*CC + 2*l), v);
            uint32_t ph, pl; cvt_hilo(v, ph, pl);
            wAhi[px*36 + l] = ph;
            wAlo[px*36 + l] = pl;
        }
        {
            const uint4* gBh = (const uint4*)(g_Wbh + (size_t)kc*4096 + brow*64);
            const uint4* gBl = (const uint4*)(g_Wbl + (size_t)kc*4096 + brow*64);
            #pragma unroll
            for (int u=0;u<2;u++){
                sBh[brow*9 + bq2 + u] = __ldg(gBh + bq2 + u);
                sBl[brow*9 + bq2 + u] = __ldg(gBl + bq2 + u);
            }
        }
        __syncthreads();

        #pragma unroll
        for (int ks=0; ks<4; ks++){
            uint32_t ah[2][4], al[2][4], bh[4], bl[4];
            #pragma unroll
            for (int mf=0; mf<2; mf++){
                uint32_t off = (uint32_t)((m0 + mf*16 + a_row)*9 + ks*2 + a_kb)*16u;
                ldsm4(ah[mf], aBase  + off);
                ldsm4(al[mf], alBase + off);
            }
            {
                uint32_t off = (uint32_t)((n0 + b_row)*9 + ks*2 + b_kb)*16u;
                ldsm4(bh, bhBase + off);
                ldsm4(bl, blBase + off);
            }
            #pragma unroll
            for (int mf=0; mf<2; mf++){
                #pragma unroll
                for (int nf=0; nf<2; nf++){
                    hmma(acc[mf][nf], ah[mf], bh[nf*2], bh[nf*2+1]);
                    hmma(acc[mf][nf], ah[mf], bl[nf*2], bl[nf*2+1]);
                    hmma(acc[mf][nf], al[mf], bh[nf*2], bh[nf*2+1]);
                }
            }
        }
    }

    __syncthreads();
    float* st = (float*)smem;
    {
        int group = l >> 2, tid4 = l & 3;
        #pragma unroll
        for (int mf=0; mf<2; mf++){
            int r0 = m0 + mf*16 + group;
            #pragma unroll
            for (int nf=0; nf<2; nf++){
                int o = n0 + nf*8 + 2*tid4;
                st[(size_t)o    *68 + r0    ] = acc[mf][nf][0];
                st[(size_t)(o+1)*68 + r0    ] = acc[mf][nf][1];
                st[(size_t)o    *68 + r0 + 8] = acc[mf][nf][2];
                st[(size_t)(o+1)*68 + r0 + 8] = acc[mf][nf][3];
            }
        }
    }
    __syncthreads();
    #pragma unroll
    for (int q=0;q<4;q++){
        int o   = q*16 + w*2 + (l >> 4);
        int px4 = (l & 15)*4;
        float4 v = *(float4*)&st[(size_t)o*68 + px4];
        *(float4*)(out + ((size_t)(b*OO + o))*HWSZ + hw0 + px4) = v;
    }
}

// ---------------- launch ------------------------------------------------------
extern "C" void kernel_launch(void* const* d_in, const int* in_sizes, int n_in,
                              void* d_out, int out_size){
    const float* x        = (const float*)d_in[0];
    const float* w_main   = (const float*)d_in[1];
    const float* w_offset = (const float*)d_in[2];
    const float* b_offset = (const float*)d_in[3];
    const float* w_mask   = (const float*)d_in[4];
    const float* b_mask   = (const float*)d_in[5];
    float* out = (float*)d_out;

    int prep_n = 9*64*64 + 9*32*64;
    k_prep<<<(prep_n + TPB-1)/TPB, TPB>>>(w_main, w_offset, w_mask);
    dim3 gx(HWSZ/32, CC/32, BB);
    k_xt<<<gx, dim3(32,8)>>>(x);
    k_om<<<NPIX/128, TPB>>>(b_offset, b_mask);
    k_fuse<<<NPIX/64, TPB>>>(out);
}